// round 15
// baseline (speedup 1.0000x reference)
#include <cuda_runtime.h>
#include <cuda_bf16.h>
#include <math.h>

#define IH 1024
#define IW 1024
#define NB 8
#define CH (IH * IW)
#define TW 32
#define TH 64
#define SIW 40   // s_img stride; col c <-> gx = x0-4+c, row r <-> gy = y0-3+r
#define SW  36   // s_gm / s_k / s_t stride
                 // s_gm/s_k: row r <-> gy = y0-2+r (0..67), col c <-> gx = x0-2+c (0..35)
                 // s_t:      row r <-> gy = y0-1+r (0..65), col c <-> gx = x0-1+c (0..33)

// tan((2k+1)*pi/16)
#define T0 0.1989123673796580f
#define T1 0.6681786379192989f
#define T2 1.4966057626654890f
#define T3 5.0273394921258481f
#define INV3 0.3333333333333333f

__device__ __forceinline__ int quant_q(float sx, float sy) {
    float ax = fabsf(sx), ay = fabsf(sy);
    int mm = (int)(ay > T0 * ax) + (int)(ay > T1 * ax)
           + (int)(ay > T2 * ax) + (int)(ay > T3 * ax);
    int neg = (__float_as_int(sx) ^ __float_as_int(sy)) < 0;
    return neg ? 4 - mm : 4 + mm;
}

// sobel at gm-coord (R,C): taps s_img rows R..R+2, cols C+1..C+3 (canonical u/v form)
__device__ __forceinline__ void sobel_at(const float* __restrict__ s_img, int R, int C,
                                         float& sx, float& sy) {
    const float* ip = s_img + R * SIW + (C + 1);
    float a0 = ip[0],       a1 = ip[1],           a2 = ip[2];
    float b0 = ip[SIW],                           b2 = ip[SIW + 2];
    float c0 = ip[2 * SIW], c1 = ip[2 * SIW + 1], c2 = ip[2 * SIW + 2];
    float u0 = a2 - a0, v0 = 0.5f * (a0 + a2) + a1;
    float u1 = b2 - b0;
    float u2 = c2 - c0, v2 = 0.5f * (c0 + c2) + c1;
    sx = (0.5f * (u0 + u2) + u1) * INV3;
    sy = (v2 - v0) * INV3;
}

// thin-edge code {0,1,2}; t = code * 0.5 exactly
__device__ __forceinline__ int nms_code(int k, float gmc,
                                        float g00, float g01, float g02,
                                        float g10,            float g12,
                                        float g20, float g21, float g22) {
    float mx0 = fmaxf(g10, g12);   // k=0: (0,±1)
    float mx1 = fmaxf(g02, g20);   // k=1: (-1,1)/(1,-1)
    float mx2 = fmaxf(g01, g21);   // k=2: (±1,0)
    float mx3 = fmaxf(g00, g22);   // k=3: (-1,-1)/(1,1)
    float mxa = (k & 1) ? mx1 : mx0;
    float mxb = (k & 1) ? mx3 : mx2;
    float mx  = (k & 2) ? mxb : mxa;
    float thin = (gmc > mx) ? gmc : 0.0f;
    return (int)(thin > 0.5f) + (int)(thin > 1.0f);
}

template<bool EDGE>
__device__ __forceinline__ void body(
    const float* __restrict__ imgb, float* __restrict__ out,
    int b, int x0, int y0, int tid,
    float* __restrict__ s_img, float* __restrict__ s_gm,
    unsigned char* __restrict__ s_k, unsigned char* __restrict__ s_t)
{
    const size_t plane = (size_t)NB * CH;
    float* o_gx = out;
    float* o_gy = out + plane;
    float* o_gm = out + 2 * plane;
    float* o_or = out + 3 * plane;
    float* o_te = out + 4 * plane;

    const int tx2 = tid & 15;    // column-pair index (0..15)
    const int tyy = tid >> 4;    // row-band index (0..15), 4 rows each

    // ---- P1: channel-summed image, rows 0..69 x cols 0..39 ----
    if (!EDGE) {
        const float4* base = (const float4*)(imgb + (size_t)(y0 - 3) * IW + (x0 - 4));
        #pragma unroll
        for (int p = 0; p < 3; p++) {
            int idx = tid + 256 * p;
            if (idx < 700) {
                int r = idx / 10, c4 = idx % 10;
                const float4* ptr = base + r * (IW / 4) + c4;
                float4 v0 = ptr[0], v1 = ptr[CH / 4], v2 = ptr[2 * (CH / 4)];
                float4 s;
                s.x = v0.x + v1.x + v2.x; s.y = v0.y + v1.y + v2.y;
                s.z = v0.z + v1.z + v2.z; s.w = v0.w + v1.w + v2.w;
                *(float4*)&s_img[r * SIW + c4 * 4] = s;
            }
        }
    } else {
        #pragma unroll
        for (int p = 0; p < 11; p++) {
            int idx = tid + 256 * p;
            if (idx < 2800) {
                int r = idx / 40, c = idx % 40;
                int gy = y0 - 3 + r, gx = x0 - 4 + c;
                float v = 0.0f;
                if ((unsigned)gy < IH && (unsigned)gx < IW) {
                    size_t o = (size_t)gy * IW + gx;
                    v = imgb[o] + imgb[o + CH] + imgb[o + 2 * CH];
                }
                s_img[r * SIW + c] = v;
            }
        }
    }
    __syncthreads();

    unsigned int kpack = 0;   // bits 4j / 4j+2: k code of (row j, col a/b)

    // ---- P2: gm + 4 output planes. main: 2 cols x 4 rows per thread ----
    auto p2_at = [&](int r, int c) {   // tails; k to s_k
        float sx, sy;
        sobel_at(s_img, r, c, sx, sy);
        float gm = sqrtf(sx * sx + sy * sy);
        int q = quant_q(sx, sy);
        if (EDGE) {
            int gy = y0 - 2 + r, gx = x0 - 2 + c;
            if (!((unsigned)gy < IH && (unsigned)gx < IW)) gm = 0.f;
        }
        s_gm[r * SW + c] = gm;
        s_k[r * SW + c] = (unsigned char)(q & 3);
    };
    {   // main: gm rows r0..r0+3 (2..65), cols c=2*tx2+2, c+1 (2..33). Always in-image.
        int r0 = 2 + 4 * tyy, c = 2 * tx2 + 2;
        const float* ip = s_img + r0 * SIW + (c + 1);   // img cols c+1..c+4 serve both px
        float f0 = ip[0], f1 = ip[1], f2 = ip[2], f3 = ip[3];
        float ua0 = f2 - f0, va0 = 0.5f * (f0 + f2) + f1;
        float ub0 = f3 - f1, vb0 = 0.5f * (f1 + f3) + f2;
        f0 = ip[SIW]; f1 = ip[SIW + 1]; f2 = ip[SIW + 2]; f3 = ip[SIW + 3];
        float ua1 = f2 - f0, va1 = 0.5f * (f0 + f2) + f1;
        float ub1 = f3 - f1, vb1 = 0.5f * (f1 + f3) + f2;
        size_t obase = (size_t)b * CH + (size_t)(y0 + 4 * tyy) * IW + (x0 + 2 * tx2);
        #pragma unroll
        for (int j = 0; j < 4; j++) {
            const float* rp = ip + (j + 2) * SIW;
            f0 = rp[0]; f1 = rp[1]; f2 = rp[2]; f3 = rp[3];
            float ua2 = f2 - f0, va2 = 0.5f * (f0 + f2) + f1;
            float ub2 = f3 - f1, vb2 = 0.5f * (f1 + f3) + f2;
            float sxa = (0.5f * (ua0 + ua2) + ua1) * INV3;
            float sya = (va2 - va0) * INV3;
            float sxb = (0.5f * (ub0 + ub2) + ub1) * INV3;
            float syb = (vb2 - vb0) * INV3;
            float gma = sqrtf(sxa * sxa + sya * sya);
            float gmb = sqrtf(sxb * sxb + syb * syb);
            int qa = quant_q(sxa, sya);
            int qb = quant_q(sxb, syb);
            *(float2*)&s_gm[(r0 + j) * SW + c] = make_float2(gma, gmb);
            kpack |= ((unsigned int)(qa & 3) << (4 * j))
                   | ((unsigned int)(qb & 3) << (4 * j + 2));
            float qva = (float)qa * 45.0f;
            if (sxa == 0.0f && sya == 0.0f) qva = __int_as_float(0x7fc00000);
            float qvb = (float)qb * 45.0f;
            if (sxb == 0.0f && syb == 0.0f) qvb = __int_as_float(0x7fc00000);
            size_t o = obase + (size_t)j * IW;
            __stcs((float2*)(o_gx + o), make_float2(sxa, sxb));
            __stcs((float2*)(o_gy + o), make_float2(sya, syb));
            __stcs((float2*)(o_gm + o), make_float2(gma, gmb));
            __stcs((float2*)(o_or + o), make_float2(qva, qvb));
            ua0 = ua1; ua1 = ua2; va0 = va1; va1 = va2;
            ub0 = ub1; ub1 = ub2; vb0 = vb1; vb1 = vb2;
        }
    }
    // tails: rows {0,1,66,67} x cols 0..35 (144) + rows 2..65 x cols {0,1,34,35} (256)
    if (tid < 144) {
        int rr = tid / 36, c = tid % 36;
        p2_at((rr < 2) ? rr : 64 + rr, c);
    }
    {
        int r = 2 + (tid >> 2);
        int m = tid & 3;
        int c = (m < 2) ? m : 32 + m;   // 0,1,34,35
        p2_at(r, c);
    }
    __syncthreads();

    // ---- P3: pure NMS -> t codes (2 cols x 4 rows; k from kpack) ----
    unsigned int tpack = 0;
    auto p3_at = [&](int r, int c) {    // tails: k from s_k
        const float* gp = s_gm + r * SW + c;
        int k = s_k[(r + 1) * SW + (c + 1)];
        int code = nms_code(k, gp[SW + 1], gp[0], gp[1], gp[2], gp[SW], gp[SW + 2],
                            gp[2 * SW], gp[2 * SW + 1], gp[2 * SW + 2]);
        if (EDGE) {
            int gy = y0 - 1 + r, gx = x0 - 1 + c;
            if (!((unsigned)gy < IH && (unsigned)gx < IW)) code = 0;
        }
        s_t[r * SW + c] = (unsigned char)code;
    };
    {   // main: t rows r0..r0+3 (1..64), cols c=2*tx2+1, c+1 (1..32). In-image.
        int r0 = 1 + 4 * tyy, c = 2 * tx2 + 1;
        const float* gp = s_gm + r0 * SW + c;
        float gA0 = gp[0],  gA1 = gp[1],      gA2 = gp[2],      gA3 = gp[3];
        float gB0 = gp[SW], gB1 = gp[SW + 1], gB2 = gp[SW + 2], gB3 = gp[SW + 3];
        #pragma unroll
        for (int j = 0; j < 4; j++) {
            int r = r0 + j;
            const float* gq = s_gm + (r + 2) * SW + c;
            float gC0 = gq[0], gC1 = gq[1], gC2 = gq[2], gC3 = gq[3];
            int ka = (kpack >> (4 * j)) & 3;       // k at (r+1, c+1)
            int kb = (kpack >> (4 * j + 2)) & 3;   // k at (r+1, c+2)
            int ca = nms_code(ka, gB1, gA0, gA1, gA2, gB0, gB2, gC0, gC1, gC2);
            int cb = nms_code(kb, gB2, gA1, gA2, gA3, gB1, gB3, gC1, gC2, gC3);
            s_t[r * SW + c]     = (unsigned char)ca;
            s_t[r * SW + c + 1] = (unsigned char)cb;
            tpack |= ((unsigned int)ca << (4 * j)) | ((unsigned int)cb << (4 * j + 2));
            gA0 = gB0; gA1 = gB1; gA2 = gB2; gA3 = gB3;
            gB0 = gC0; gB1 = gC1; gB2 = gC2; gB3 = gC3;
        }
    }
    if (tid < 68) {             // tail A: rows {0,65} x cols 0..33
        int rr = tid / 34, c = tid % 34;
        p3_at(rr ? 65 : 0, c);
    } else if (tid < 196) {     // tail B: rows 1..64 x cols {0,33}
        int k2 = tid - 68;
        p3_at(1 + (k2 >> 1), (k2 & 1) ? 33 : 0);
    }
    __syncthreads();

    // ---- P4: thin-edges (integer hysteresis; 2 cols x 4 rows; tc from tpack) ----
    {
        int r0 = 4 * tyy, ix = 2 * tx2;
        const unsigned char* tp = s_t + r0 * SW + ix;   // even offset: uchar2 aligned
        uchar2 q0 = *(const uchar2*)tp;
        uchar2 q1 = *(const uchar2*)(tp + 2);
        int sa0 = q0.x + q0.y + q1.x, sb0 = q0.y + q1.x + q1.y;
        q0 = *(const uchar2*)(tp + SW);
        q1 = *(const uchar2*)(tp + SW + 2);
        int sa1 = q0.x + q0.y + q1.x, sb1 = q0.y + q1.x + q1.y;
        size_t obase = (size_t)b * CH + (size_t)(y0 + r0) * IW + (x0 + ix);
        #pragma unroll
        for (int j = 0; j < 4; j++) {
            q0 = *(const uchar2*)(tp + (j + 2) * SW);
            q1 = *(const uchar2*)(tp + (j + 2) * SW + 2);
            int sa2 = q0.x + q0.y + q1.x, sb2 = q0.y + q1.x + q1.y;
            int Sa = sa0 + sa1 + sa2, Sb = sb0 + sb1 + sb2;
            int tca = (tpack >> (4 * j)) & 3;
            int tcb = (tpack >> (4 * j + 2)) & 3;
            // sum*1.25 > 1 <=> S >= 2 (S = 2*sum); high <=> tc==2
            float tea = (tca == 2 || (tca == 1 && Sa >= 2)) ? 1.0f : 0.0f;
            float teb = (tcb == 2 || (tcb == 1 && Sb >= 2)) ? 1.0f : 0.0f;
            __stcs((float2*)(o_te + obase + (size_t)j * IW), make_float2(tea, teb));
            sa0 = sa1; sa1 = sa2; sb0 = sb1; sb1 = sb2;
        }
    }
}

__global__ __launch_bounds__(256, 5)
void canny_fused_kernel(const float* __restrict__ img, float* __restrict__ out)
{
    __shared__ __align__(16) float s_img[70 * SIW];            // 11200 B
    __shared__ __align__(16) float s_gm [68 * SW + 8];         //  9856 B
    __shared__ unsigned char s_k[68 * SW + 8];                 //  2456 B (tails only)
    __shared__ __align__(4) unsigned char s_t[66 * SW + 8];    //  2384 B

    const int b  = blockIdx.z;
    const int x0 = blockIdx.x * TW;
    const int y0 = blockIdx.y * TH;
    const int tid = threadIdx.y * 32 + threadIdx.x;

    const float* imgb = img + (size_t)b * 3 * CH;

    const bool edge = (x0 == 0) || (y0 == 0) || (x0 + TW == IW) || (y0 + TH == IH);
    if (edge)
        body<true >(imgb, out, b, x0, y0, tid, s_img, s_gm, s_k, s_t);
    else
        body<false>(imgb, out, b, x0, y0, tid, s_img, s_gm, s_k, s_t);
}

extern "C" void kernel_launch(void* const* d_in, const int* in_sizes, int n_in,
                              void* d_out, int out_size)
{
    const float* img = (const float*)d_in[0];
    float* out = (float*)d_out;
    dim3 block(32, 8, 1);
    dim3 grid(IW / TW, IH / TH, NB);
    canny_fused_kernel<<<grid, block>>>(img, out);
}

// round 17
// speedup vs baseline: 1.0697x; 1.0697x over previous
#include <cuda_runtime.h>
#include <cuda_bf16.h>
#include <math.h>

#define IH 1024
#define IW 1024
#define NB 8
#define CH (IH * IW)
#define TW 32
#define TH 64
#define SIW 40   // s_img stride; col c <-> gx = x0-4+c, row r <-> gy = y0-3+r
#define SG  38   // s_gm stride; col c <-> gx = x0-3+c (1..36 used), row r <-> gy = y0-2+r (0..67)
#define ST  36   // s_t stride;  col c <-> gx = x0-1+c (0..33 used), row r <-> gy = y0-1+r (0..65)

// tan((2k+1)*pi/16)
#define T0 0.1989123673796580f
#define T1 0.6681786379192989f
#define T2 1.4966057626654890f
#define T3 5.0273394921258481f
#define INV3 0.3333333333333333f

__device__ __forceinline__ int quant_q(float sx, float sy) {
    float ax = fabsf(sx), ay = fabsf(sy);
    int mm = (int)(ay > T0 * ax) + (int)(ay > T1 * ax)
           + (int)(ay > T2 * ax) + (int)(ay > T3 * ax);
    int neg = (__float_as_int(sx) ^ __float_as_int(sy)) < 0;
    return neg ? 4 - mm : 4 + mm;
}

// sobel at OLD gm-coord (R,C) <-> gy = y0-2+R, gx = x0-2+C; taps s_img rows R..R+2, cols C+1..C+3
__device__ __forceinline__ void sobel_at(const float* __restrict__ s_img, int R, int C,
                                         float& sx, float& sy) {
    const float* ip = s_img + R * SIW + (C + 1);
    float a0 = ip[0],       a1 = ip[1],           a2 = ip[2];
    float b0 = ip[SIW],                           b2 = ip[SIW + 2];
    float c0 = ip[2 * SIW], c1 = ip[2 * SIW + 1], c2 = ip[2 * SIW + 2];
    float u0 = a2 - a0, v0 = 0.5f * (a0 + a2) + a1;
    float u1 = b2 - b0;
    float u2 = c2 - c0, v2 = 0.5f * (c0 + c2) + c1;
    sx = (0.5f * (u0 + u2) + u1) * INV3;
    sy = (v2 - v0) * INV3;
}

// thin-edge code {0,1,2}; t = code * 0.5 exactly
__device__ __forceinline__ int nms_code(int k, float gmc,
                                        float g00, float g01, float g02,
                                        float g10,            float g12,
                                        float g20, float g21, float g22) {
    float mx0 = fmaxf(g10, g12);   // k=0: (0,±1)
    float mx1 = fmaxf(g02, g20);   // k=1: (-1,1)/(1,-1)
    float mx2 = fmaxf(g01, g21);   // k=2: (±1,0)
    float mx3 = fmaxf(g00, g22);   // k=3: (-1,-1)/(1,1)
    float mxa = (k & 1) ? mx1 : mx0;
    float mxb = (k & 1) ? mx3 : mx2;
    float mx  = (k & 2) ? mxb : mxa;
    float thin = (gmc > mx) ? gmc : 0.0f;
    return (int)(thin > 0.5f) + (int)(thin > 1.0f);
}

template<bool EDGE>
__device__ __forceinline__ void body(
    const float* __restrict__ imgb, float* __restrict__ out,
    int b, int x0, int y0, int tid,
    float* __restrict__ s_img, float* __restrict__ s_gm,
    unsigned char* __restrict__ s_t)
{
    const size_t plane = (size_t)NB * CH;
    float* o_gx = out;
    float* o_gy = out + plane;
    float* o_gm = out + 2 * plane;
    float* o_or = out + 3 * plane;
    float* o_te = out + 4 * plane;

    const int tx2 = tid & 15;    // column-pair index (0..15)
    const int tyy = tid >> 4;    // row-band index (0..15), 4 rows each

    // ---- P1: channel-summed image, rows 0..69 x 10 float4 groups (cols 0..39) ----
    {
        #pragma unroll
        for (int p = 0; p < 3; p++) {
            int idx = tid + 256 * p;
            if (idx < 700) {
                int r = idx / 10, g = idx % 10;
                float4 s = make_float4(0.f, 0.f, 0.f, 0.f);
                if (!EDGE) {
                    const float4* ptr = (const float4*)(imgb + (size_t)(y0 - 3 + r) * IW
                                                        + (x0 - 4) + 4 * g);
                    float4 v0 = ptr[0], v1 = ptr[CH / 4], v2 = ptr[2 * (CH / 4)];
                    s.x = v0.x + v1.x + v2.x; s.y = v0.y + v1.y + v2.y;
                    s.z = v0.z + v1.z + v2.z; s.w = v0.w + v1.w + v2.w;
                } else {
                    int gy = y0 - 3 + r;
                    int gx0 = x0 - 4 + 4 * g;
                    if ((unsigned)gy < IH) {
                        if (gx0 >= 0 && gx0 + 3 < IW) {   // aligned interior group
                            const float4* ptr = (const float4*)(imgb + (size_t)gy * IW + gx0);
                            float4 v0 = ptr[0], v1 = ptr[CH / 4], v2 = ptr[2 * (CH / 4)];
                            s.x = v0.x + v1.x + v2.x; s.y = v0.y + v1.y + v2.y;
                            s.z = v0.z + v1.z + v2.z; s.w = v0.w + v1.w + v2.w;
                        } else {
                            float tmp[4] = {0.f, 0.f, 0.f, 0.f};
                            #pragma unroll
                            for (int e = 0; e < 4; e++) {
                                int gx = gx0 + e;
                                if ((unsigned)gx < IW) {
                                    const float* q = imgb + (size_t)gy * IW + gx;
                                    tmp[e] = q[0] + q[CH] + q[2 * CH];
                                }
                            }
                            s = make_float4(tmp[0], tmp[1], tmp[2], tmp[3]);
                        }
                    }
                }
                *(float4*)&s_img[r * SIW + 4 * g] = s;
            }
        }
    }
    __syncthreads();

    unsigned int kpack = 0;   // bits 4j / 4j+2: k code of (row j, col a/b)

    // ---- P2: gm + 4 output planes. main: 2 cols x 4 rows per thread ----
    // s_gm col c_new <-> gx = x0-3+c_new (c_new = C_old + 1)
    auto p2_at = [&](int r, int cn) {   // tails; cn = new gm col (1..36)
        float sx, sy;
        sobel_at(s_img, r, cn - 1, sx, sy);
        float gm = sqrtf(sx * sx + sy * sy);
        if (EDGE) {
            int gy = y0 - 2 + r, gx = x0 - 3 + cn;
            if (!((unsigned)gy < IH && (unsigned)gx < IW)) gm = 0.f;
        }
        s_gm[r * SG + cn] = gm;
    };
    {   // main: gm rows r0..r0+3 (2..65), px gx = x0+2*tx2+{0,1} -> new cols 2*tx2+3, +4
        int r0 = 2 + 4 * tyy;
        int cn = 2 * tx2 + 3;
        const float* ip = s_img + r0 * SIW + (2 * tx2 + 3);  // img cols serve both px
        float f0 = ip[0], f1 = ip[1], f2 = ip[2], f3 = ip[3];
        float ua0 = f2 - f0, va0 = 0.5f * (f0 + f2) + f1;
        float ub0 = f3 - f1, vb0 = 0.5f * (f1 + f3) + f2;
        f0 = ip[SIW]; f1 = ip[SIW + 1]; f2 = ip[SIW + 2]; f3 = ip[SIW + 3];
        float ua1 = f2 - f0, va1 = 0.5f * (f0 + f2) + f1;
        float ub1 = f3 - f1, vb1 = 0.5f * (f1 + f3) + f2;
        size_t obase = (size_t)b * CH + (size_t)(y0 + 4 * tyy) * IW + (x0 + 2 * tx2);
        #pragma unroll
        for (int j = 0; j < 4; j++) {
            const float* rp = ip + (j + 2) * SIW;
            f0 = rp[0]; f1 = rp[1]; f2 = rp[2]; f3 = rp[3];
            float ua2 = f2 - f0, va2 = 0.5f * (f0 + f2) + f1;
            float ub2 = f3 - f1, vb2 = 0.5f * (f1 + f3) + f2;
            float sxa = (0.5f * (ua0 + ua2) + ua1) * INV3;
            float sya = (va2 - va0) * INV3;
            float sxb = (0.5f * (ub0 + ub2) + ub1) * INV3;
            float syb = (vb2 - vb0) * INV3;
            float gma = sqrtf(sxa * sxa + sya * sya);
            float gmb = sqrtf(sxb * sxb + syb * syb);
            int qa = quant_q(sxa, sya);
            int qb = quant_q(sxb, syb);
            s_gm[(r0 + j) * SG + cn]     = gma;
            s_gm[(r0 + j) * SG + cn + 1] = gmb;
            kpack |= ((unsigned int)(qa & 3) << (4 * j))
                   | ((unsigned int)(qb & 3) << (4 * j + 2));
            float qva = (float)qa * 45.0f;
            if (sxa == 0.0f && sya == 0.0f) qva = __int_as_float(0x7fc00000);
            float qvb = (float)qb * 45.0f;
            if (sxb == 0.0f && syb == 0.0f) qvb = __int_as_float(0x7fc00000);
            size_t o = obase + (size_t)j * IW;
            __stcs((float2*)(o_gx + o), make_float2(sxa, sxb));
            __stcs((float2*)(o_gy + o), make_float2(sya, syb));
            __stcs((float2*)(o_gm + o), make_float2(gma, gmb));
            __stcs((float2*)(o_or + o), make_float2(qva, qvb));
            ua0 = ua1; ua1 = ua2; va0 = va1; va1 = va2;
            ub0 = ub1; ub1 = ub2; vb0 = vb1; vb1 = vb2;
        }
    }
    // tails: rows {0,1,66,67} x new-cols 1..36 (144) + rows 2..65 x new-cols {1,2,35,36} (256)
    if (tid < 144) {
        int rr = tid / 36, cn = 1 + tid % 36;
        p2_at((rr < 2) ? rr : 64 + rr, cn);
    }
    {
        int r = 2 + (tid >> 2);
        int m = tid & 3;
        int cn = (m < 2) ? 1 + m : 33 + m;   // 1,2,35,36
        p2_at(r, cn);
    }
    __syncthreads();

    // ---- P3: pure NMS -> t codes (2 cols x 4 rows; k from kpack; vector gm loads) ----
    unsigned int tpack = 0;
    auto p3_at = [&](int r, int c) {    // tails: recompute k via sobel (no s_k)
        float sx, sy;
        sobel_at(s_img, r + 1, c + 1, sx, sy);
        int k = quant_q(sx, sy) & 3;
        const float* gp = s_gm + r * SG + (c + 1);   // gm new cols c+1..c+3
        int code = nms_code(k, gp[SG + 1], gp[0], gp[1], gp[2], gp[SG], gp[SG + 2],
                            gp[2 * SG], gp[2 * SG + 1], gp[2 * SG + 2]);
        if (EDGE) {
            int gy = y0 - 1 + r, gx = x0 - 1 + c;
            if (!((unsigned)gy < IH && (unsigned)gx < IW)) code = 0;
        }
        s_t[r * ST + c] = (unsigned char)code;
    };
    {   // main: t rows r0..r0+3 (1..64), t cols c = 2*tx2+1, c+1. gm new cols 2*tx2+2..+5 (even start)
        int r0 = 1 + 4 * tyy, c = 2 * tx2 + 1;
        const float* gp = s_gm + r0 * SG + (2 * tx2 + 2);
        float2 gA01 = *(const float2*)gp,        gA23 = *(const float2*)(gp + 2);
        float2 gB01 = *(const float2*)(gp + SG), gB23 = *(const float2*)(gp + SG + 2);
        float gA0 = gA01.x, gA1 = gA01.y, gA2 = gA23.x, gA3 = gA23.y;
        float gB0 = gB01.x, gB1 = gB01.y, gB2 = gB23.x, gB3 = gB23.y;
        #pragma unroll
        for (int j = 0; j < 4; j++) {
            int r = r0 + j;
            const float* gq = gp + (j + 2) * SG;
            float2 gC01 = *(const float2*)gq, gC23 = *(const float2*)(gq + 2);
            float gC0 = gC01.x, gC1 = gC01.y, gC2 = gC23.x, gC3 = gC23.y;
            int ka = (kpack >> (4 * j)) & 3;       // k at (r+1, c+1)
            int kb = (kpack >> (4 * j + 2)) & 3;   // k at (r+1, c+2)
            int ca = nms_code(ka, gB1, gA0, gA1, gA2, gB0, gB2, gC0, gC1, gC2);
            int cb = nms_code(kb, gB2, gA1, gA2, gA3, gB1, gB3, gC1, gC2, gC3);
            s_t[r * ST + c]     = (unsigned char)ca;
            s_t[r * ST + c + 1] = (unsigned char)cb;
            tpack |= ((unsigned int)ca << (4 * j)) | ((unsigned int)cb << (4 * j + 2));
            gA0 = gB0; gA1 = gB1; gA2 = gB2; gA3 = gB3;
            gB0 = gC0; gB1 = gC1; gB2 = gC2; gB3 = gC3;
        }
    }
    if (tid < 68) {             // tail A: rows {0,65} x cols 0..33
        int rr = tid / 34, c = tid % 34;
        p3_at(rr ? 65 : 0, c);
    } else if (tid < 196) {     // tail B: rows 1..64 x cols {0,33}
        int k2 = tid - 68;
        p3_at(1 + (k2 >> 1), (k2 & 1) ? 33 : 0);
    }
    __syncthreads();

    // ---- P4: thin-edges (integer hysteresis; 2 cols x 4 rows; tc from tpack) ----
    {
        int r0 = 4 * tyy, ix = 2 * tx2;
        const unsigned char* tp = s_t + r0 * ST + ix;   // even offset: uchar2 aligned
        uchar2 q0 = *(const uchar2*)tp;
        uchar2 q1 = *(const uchar2*)(tp + 2);
        int sa0 = q0.x + q0.y + q1.x, sb0 = q0.y + q1.x + q1.y;
        q0 = *(const uchar2*)(tp + ST);
        q1 = *(const uchar2*)(tp + ST + 2);
        int sa1 = q0.x + q0.y + q1.x, sb1 = q0.y + q1.x + q1.y;
        size_t obase = (size_t)b * CH + (size_t)(y0 + r0) * IW + (x0 + ix);
        #pragma unroll
        for (int j = 0; j < 4; j++) {
            q0 = *(const uchar2*)(tp + (j + 2) * ST);
            q1 = *(const uchar2*)(tp + (j + 2) * ST + 2);
            int sa2 = q0.x + q0.y + q1.x, sb2 = q0.y + q1.x + q1.y;
            int Sa = sa0 + sa1 + sa2, Sb = sb0 + sb1 + sb2;
            int tca = (tpack >> (4 * j)) & 3;
            int tcb = (tpack >> (4 * j + 2)) & 3;
            // sum*1.25 > 1 <=> S >= 2 (S = 2*sum); high <=> tc==2
            float tea = (tca == 2 || (tca == 1 && Sa >= 2)) ? 1.0f : 0.0f;
            float teb = (tcb == 2 || (tcb == 1 && Sb >= 2)) ? 1.0f : 0.0f;
            __stcs((float2*)(o_te + obase + (size_t)j * IW), make_float2(tea, teb));
            sa0 = sa1; sa1 = sa2; sb0 = sb1; sb1 = sb2;
        }
    }
}

__global__ __launch_bounds__(256, 6)
void canny_fused_kernel(const float* __restrict__ img, float* __restrict__ out)
{
    __shared__ __align__(16) float s_img[70 * SIW];            // 11200 B
    __shared__ __align__(16) float s_gm [68 * SG + 8];         // 10368 B
    __shared__ __align__(4)  unsigned char s_t[66 * ST + 8];   //  2384 B  (total ~23.9 KB)

    const int b  = blockIdx.z;
    const int x0 = blockIdx.x * TW;
    const int y0 = blockIdx.y * TH;
    const int tid = threadIdx.y * 32 + threadIdx.x;

    const float* imgb = img + (size_t)b * 3 * CH;

    const bool edge = (x0 == 0) || (y0 == 0) || (x0 + TW == IW) || (y0 + TH == IH);
    if (edge)
        body<true >(imgb, out, b, x0, y0, tid, s_img, s_gm, s_t);
    else
        body<false>(imgb, out, b, x0, y0, tid, s_img, s_gm, s_t);
}

extern "C" void kernel_launch(void* const* d_in, const int* in_sizes, int n_in,
                              void* d_out, int out_size)
{
    const float* img = (const float*)d_in[0];
    float* out = (float*)d_out;
    dim3 block(32, 8, 1);
    dim3 grid(IW / TW, IH / TH, NB);
    canny_fused_kernel<<<grid, block>>>(img, out);
}